// round 16
// baseline (speedup 1.0000x reference)
#include <cuda_runtime.h>
#include <cuda_fp16.h>

#define B_DIM 2048
#define IN_DIM 8192
#define O_DIM 4096
#define K_DIM 64

// 32 MB transposed fp16 copy of x: xth[i][b] (b contiguous, L2-resident)
__device__ __half g_xth[(size_t)IN_DIM * B_DIM];

// ---------------------------------------------------------------------------
// Kernel 1: transpose+convert x[B, IN] f32 -> g_xth[IN, B] f16.
// R11 version (measured ~12us, near the 96MB DRAM/LTS floor). Unchanged.
// ---------------------------------------------------------------------------
#define TPITCH 76

__global__ __launch_bounds__(256) void transpose_kernel(const float* __restrict__ x) {
    __shared__ __half2 st2[32][TPITCH];
    const int i0 = blockIdx.x * 64;
    const int b0 = blockIdx.y * 64;
    const int t = threadIdx.x;

    {
        const int r = t >> 2;
        const int c = t & 3;
        const float4* __restrict__ xr = (const float4*)(x + (size_t)(b0 + r) * IN_DIM + i0);
#pragma unroll
        for (int j = 0; j < 4; j++) {
            const float4 f = xr[c + 4 * j];
            const int i2 = 2 * c + 8 * j;
            st2[i2 + 0][r] = __floats2half2_rn(f.x, f.y);
            st2[i2 + 1][r] = __floats2half2_rn(f.z, f.w);
        }
    }
    __syncthreads();
    {
        const int p2 = t >> 4;
        const int m = t & 15;
        const int bb = 4 * m;
#pragma unroll
        for (int pp = 0; pp < 2; pp++) {
            const int p = 2 * p2 + pp;
            const uint4 u = *(const uint4*)&st2[p][bb];
            unsigned int lo0 = __byte_perm(u.x, u.y, 0x5410);
            unsigned int lo1 = __byte_perm(u.z, u.w, 0x5410);
            unsigned int hi0 = __byte_perm(u.x, u.y, 0x7632);
            unsigned int hi1 = __byte_perm(u.z, u.w, 0x7632);
            __half* __restrict__ row0 = g_xth + (size_t)(i0 + 2 * p + 0) * B_DIM + b0 + bb;
            __half* __restrict__ row1 = g_xth + (size_t)(i0 + 2 * p + 1) * B_DIM + b0 + bb;
            *(uint2*)row0 = make_uint2(lo0, lo1);
            *(uint2*)row1 = make_uint2(hi0, hi1);
        }
    }
}

// ---------------------------------------------------------------------------
// Kernel 2: gather + weighted reduce (fp16 xt, HFMA2 4-k partials, fp32 acc).
// R15 base (gather 82.1us; issue/L2/L1 three-way ~55-64%) + fp-stream diet:
// per 4-k group per j: 2 LDS.128 + 4 LDG.128 + 16 HFMA2 (4 indep chains,
// depth 4) + 1 flush -> ~32 instr vs R15's ~54.
// R14's HFMA2 attempt failed at 48 regs (MLP collapse); this keeps
// launch_bounds(256,4) so regs stay ~64 -- isolating the HFMA2 variable.
// w staged pre-duplicated (w|w). rel_err of this accumulation pattern
// MEASURED in R14: 4.40e-4 (budget 1e-3).
// ---------------------------------------------------------------------------
#define OT 4
#define NTHR 256
#define K2 (K_DIM / 2)

__global__ __launch_bounds__(NTHR, 4) void gather_kernel(const int* __restrict__ indices,
                                                         const float* __restrict__ weight,
                                                         const float* __restrict__ bias,
                                                         float* __restrict__ out) {
    __shared__ int4 s_iw4[OT * K2];  // 2 KB: paired {off0, ww0, off1, ww1}

    const int tid = threadIdx.x;
    const int obase = blockIdx.y * OT;
    const int brow = tid * 8;  // first of this thread's 8 b's

    // Stage paired refs: threads 0..127 build one int4 each (OT*K2 == 128).
    // Weights stored as duplicated half2 (w|w).
    if (tid < OT * K2) {
        const int j = tid >> 5;  // o_local
        const int k2 = tid & 31;
        const size_t base = (size_t)(obase + j) * K_DIM + 2 * k2;
        const unsigned int h0 = __half_as_ushort(__float2half(weight[base + 0]));
        const unsigned int h1 = __half_as_ushort(__float2half(weight[base + 1]));
        int4 p;
        p.x = indices[base + 0] * (B_DIM / 8);
        p.y = (int)((h0 << 16) | h0);
        p.z = indices[base + 1] * (B_DIM / 8);
        p.w = (int)((h1 << 16) | h1);
        s_iw4[j * K2 + k2] = p;
    }
    __syncthreads();

    const uint4* __restrict__ xt8 = (const uint4*)g_xth;

    float facc[OT][8];
#pragma unroll
    for (int j = 0; j < OT; j++)
#pragma unroll
        for (int q = 0; q < 8; q++) facc[j][q] = 0.f;

    // k4 = group of 4 k (two staged pairs). 16 groups.
    for (int k4 = 0; k4 < K_DIM / 4; k4++) {
#pragma unroll
        for (int j = 0; j < OT; j++) {
            const int4 pA = s_iw4[j * K2 + 2 * k4 + 0];  // LDS.128
            const int4 pB = s_iw4[j * K2 + 2 * k4 + 1];  // LDS.128
            const uint4 v0 = xt8[pA.x + tid];  // 4 independent LDG.128
            const uint4 v1 = xt8[pA.z + tid];
            const uint4 v2 = xt8[pB.x + tid];
            const uint4 v3 = xt8[pB.z + tid];
            const __half2 w0 = *(const __half2*)&pA.y;
            const __half2 w1 = *(const __half2*)&pA.w;
            const __half2 w2 = *(const __half2*)&pB.y;
            const __half2 w3 = *(const __half2*)&pB.w;
            const __half2* h0 = (const __half2*)&v0;
            const __half2* h1 = (const __half2*)&v1;
            const __half2* h2 = (const __half2*)&v2;
            const __half2* h3 = (const __half2*)&v3;
            // 4 independent chains (one per b-pair q), depth 4 each.
#pragma unroll
            for (int q = 0; q < 4; q++) {
                __half2 hp = __hmul2(h0[q], w0);
                hp = __hfma2(h1[q], w1, hp);
                hp = __hfma2(h2[q], w2, hp);
                hp = __hfma2(h3[q], w3, hp);
                const float2 f = __half22float2(hp);
                facc[j][2 * q + 0] += f.x;
                facc[j][2 * q + 1] += f.y;
            }
        }
    }

    float bv[OT];
#pragma unroll
    for (int j = 0; j < OT; j++) bv[j] = bias[obase + j];

    // Full-width stores: out[b][obase..obase+3] as one STG.128 per b
#pragma unroll
    for (int bb = 0; bb < 8; bb++) {
        float4 v;
        v.x = facc[0][bb] + bv[0];
        v.y = facc[1][bb] + bv[1];
        v.z = facc[2][bb] + bv[2];
        v.w = facc[3][bb] + bv[3];
        *(float4*)(out + (size_t)(brow + bb) * O_DIM + obase) = v;
    }
}

// ---------------------------------------------------------------------------
// Launch
// ---------------------------------------------------------------------------
extern "C" void kernel_launch(void* const* d_in, const int* in_sizes, int n_in,
                              void* d_out, int out_size) {
    (void)in_sizes; (void)n_in; (void)out_size;
    const float* x = (const float*)d_in[0];
    const int* indices = (const int*)d_in[1];
    const float* weight = (const float*)d_in[2];
    const float* bias = (const float*)d_in[3];
    float* out = (float*)d_out;

    dim3 tg(IN_DIM / 64, B_DIM / 64);  // (128, 32)
    transpose_kernel<<<tg, 256>>>(x);

    dim3 gg(1, O_DIM / OT);  // (1, 1024)
    gather_kernel<<<gg, NTHR>>>(indices, weight, bias, out);
}